// round 1
// baseline (speedup 1.0000x reference)
#include <cuda_runtime.h>
#include <cuda_bf16.h>

#define C            128
#define NPRED        8
#define WARPS_PER_BLOCK 8
#define THREADS      (WARPS_PER_BLOCK * 32)

// Scratch for the global max (monotonic int-mapped float). __device__ global:
// no allocations allowed in kernel_launch.
__device__ int g_max_bits;

__device__ __forceinline__ int f2ord(float x) {
    int i = __float_as_int(x);
    return (i >= 0) ? i : (i ^ 0x7FFFFFFF);
}
__device__ __forceinline__ float ord2f(int i) {
    return __int_as_float((i >= 0) ? i : (i ^ 0x7FFFFFFF));
}

__global__ void tw_init_kernel() {
    g_max_bits = 0x80000000;  // INT_MIN == smallest ordered value
}

__global__ void tw_fin_kernel(float* __restrict__ out) {
    out[0] = ord2f(g_max_bits);
}

__global__ __launch_bounds__(THREADS)
void tw_main_kernel(const float* __restrict__ p0, const float* __restrict__ p1,
                    const float* __restrict__ p2, const float* __restrict__ p3,
                    const float* __restrict__ p4, const float* __restrict__ p5,
                    const float* __restrict__ p6, const float* __restrict__ p7,
                    const int*   __restrict__ targets,
                    float* __restrict__ out)  // out_threshold region (d_out + 1)
{
    const int warp = threadIdx.x >> 5;
    const int lane = threadIdx.x & 31;
    const long long row = (long long)blockIdx.x * WARPS_PER_BLOCK + warp;

    const float* preds[NPRED] = {p0, p1, p2, p3, p4, p5, p6, p7};

    const int t     = targets[row];
    const int tlane = t >> 2;
    const int tsub  = t & 3;

    // Issue all 8 predictor loads up front: MLP = 8, coalesced 512B per warp each.
    float4 v[NPRED];
    const long long base = row * (long long)C + (long long)lane * 4;
#pragma unroll
    for (int p = 0; p < NPRED; p++) {
        v[p] = *reinterpret_cast<const float4*>(preds[p] + base);
    }

    float margins[NPRED];
    float rowmax7 = -1e30f;

#pragma unroll
    for (int p = 0; p < NPRED; p++) {
        const float4 q = v[p];
        // local multiset top-2 of 4 values
        float a = fmaxf(q.x, q.y), b = fminf(q.x, q.y);
        float c = fmaxf(q.z, q.w), d = fminf(q.z, q.w);
        float m1 = fmaxf(a, c);
        float m2 = fmaxf(fminf(a, c), fmaxf(b, d));

        // target value broadcast
        float tv = (tsub == 0) ? q.x : (tsub == 1) ? q.y : (tsub == 2) ? q.z : q.w;
        tv = __shfl_sync(0xFFFFFFFFu, tv, tlane);

        // warp multiset top-2 butterfly
#pragma unroll
        for (int off = 16; off > 0; off >>= 1) {
            float o1 = __shfl_xor_sync(0xFFFFFFFFu, m1, off);
            float o2 = __shfl_xor_sync(0xFFFFFFFFu, m2, off);
            float n1 = fmaxf(m1, o1);
            float n2 = fmaxf(fminf(m1, o1), fmaxf(m2, o2));
            m1 = n1; m2 = n2;
        }

        margins[p] = (tv == m1) ? (m1 - m2) : 0.0f;
        if (p < 7) rowmax7 = fmaxf(rowmax7, m1);
    }

    // softmax over 8 margins with T = 2.0 (all lanes compute identically)
    float mm = margins[0];
#pragma unroll
    for (int p = 1; p < NPRED; p++) mm = fmaxf(mm, margins[p]);
    float e[NPRED];
    float s = 0.0f;
#pragma unroll
    for (int p = 0; p < NPRED; p++) {
        e[p] = __expf((margins[p] - mm) * 0.5f);
        s += e[p];
    }
    const float inv = 1.0f / s;

    // lanes 0..7 write the 8 outputs (static select chain, coalesced 32B)
    float ov = e[0];
    ov = (lane == 1) ? e[1] : ov;
    ov = (lane == 2) ? e[2] : ov;
    ov = (lane == 3) ? e[3] : ov;
    ov = (lane == 4) ? e[4] : ov;
    ov = (lane == 5) ? e[5] : ov;
    ov = (lane == 6) ? e[6] : ov;
    ov = (lane == 7) ? e[7] : ov;
    if (lane < NPRED) {
        out[row * NPRED + lane] = ov * inv;
    }

    // block-level max over outputs1..7, one atomic per block
    __shared__ float sm[WARPS_PER_BLOCK];
    if (lane == 0) sm[warp] = rowmax7;
    __syncthreads();
    if (threadIdx.x == 0) {
        float bm = sm[0];
#pragma unroll
        for (int i = 1; i < WARPS_PER_BLOCK; i++) bm = fmaxf(bm, sm[i]);
        atomicMax(&g_max_bits, f2ord(bm));
    }
}

extern "C" void kernel_launch(void* const* d_in, const int* in_sizes, int n_in,
                              void* d_out, int out_size)
{
    const float* p0 = (const float*)d_in[0];
    const float* p1 = (const float*)d_in[1];
    const float* p2 = (const float*)d_in[2];
    const float* p3 = (const float*)d_in[3];
    const float* p4 = (const float*)d_in[4];
    const float* p5 = (const float*)d_in[5];
    const float* p6 = (const float*)d_in[6];
    const float* mim = (const float*)d_in[7];
    const int*   tg = (const int*)d_in[8];

    const int N = in_sizes[8];  // targets has N elements

    float* out = (float*)d_out;

    tw_init_kernel<<<1, 1>>>();

    const int rows_per_block = WARPS_PER_BLOCK;
    const int grid = (N + rows_per_block - 1) / rows_per_block;
    tw_main_kernel<<<grid, THREADS>>>(p0, p1, p2, p3, p4, p5, p6, mim,
                                      tg, out + 1);

    tw_fin_kernel<<<1, 1>>>(out);
}

// round 3
// speedup vs baseline: 1.0260x; 1.0260x over previous
#include <cuda_runtime.h>
#include <cuda_bf16.h>

#define C               128
#define NPRED           8
#define WARPS_PER_BLOCK 16
#define THREADS         (WARPS_PER_BLOCK * 32)

// Statically-initialized scratch (no allocations allowed). The finalizing
// block resets both after use, so every kernel invocation (graph replay)
// starts from identical state -> deterministic.
__device__ int      g_max_bits    = (int)0x80000000;  // ordered-int minimum
__device__ unsigned g_blocks_done = 0;

// Monotone bijection float <-> int: preserves order, ties, equality exactly.
__device__ __forceinline__ int f2ord(float x) {
    int i = __float_as_int(x);
    return (i >= 0) ? i : (i ^ 0x7FFFFFFF);
}
__device__ __forceinline__ float ord2f(int i) {
    return __int_as_float((i >= 0) ? i : (i ^ 0x7FFFFFFF));
}

// sm_103a has integer redux only (no redux.f32). Warp max over ordered ints.
__device__ __forceinline__ int warp_max_ord(int x) {
    int r;
    asm("redux.sync.max.s32 %0, %1, 0xffffffff;" : "=r"(r) : "r"(x));
    return r;
}

__global__ __launch_bounds__(THREADS)
void tw_kernel(const float* __restrict__ p0, const float* __restrict__ p1,
               const float* __restrict__ p2, const float* __restrict__ p3,
               const float* __restrict__ p4, const float* __restrict__ p5,
               const float* __restrict__ p6, const float* __restrict__ p7,
               const int*   __restrict__ targets,
               float* __restrict__ out,    // d_out (out[0] = max_preds, out+1 = [N,8])
               int nblocks)
{
    const int warp = threadIdx.x >> 5;
    const int lane = threadIdx.x & 31;
    const long long row = (long long)blockIdx.x * WARPS_PER_BLOCK + warp;

    const float* preds[NPRED] = {p0, p1, p2, p3, p4, p5, p6, p7};

    const int t     = targets[row];
    const int tlane = t >> 2;
    const int tsub  = t & 3;

    // Issue all 8 predictor loads up front: MLP = 8, coalesced 512B/warp each.
    // Streaming (evict-first): every byte is read exactly once.
    float4 v[NPRED];
    const long long base = row * (long long)C + (long long)lane * 4;
#pragma unroll
    for (int p = 0; p < NPRED; p++) {
        v[p] = __ldcs(reinterpret_cast<const float4*>(preds[p] + base));
    }

    float margins[NPRED];
    int rowmax7o = (int)0x80000000;

#pragma unroll
    for (int p = 0; p < NPRED; p++) {
        const float4 q = v[p];
        // local multiset top-2 of this lane's 4 values
        float a = fmaxf(q.x, q.y), b = fminf(q.x, q.y);
        float c = fmaxf(q.z, q.w), d = fminf(q.z, q.w);
        float m1l = fmaxf(a, c);
        float m2l = fmaxf(fminf(a, c), fmaxf(b, d));

        // target value broadcast
        float tv = (tsub == 0) ? q.x : (tsub == 1) ? q.y : (tsub == 2) ? q.z : q.w;
        tv = __shfl_sync(0xFFFFFFFFu, tv, tlane);

        // warp multiset top-2 via integer redux on the ordered mapping:
        //   M1 = max(m1l); M2 = M1 if >=2 lanes tie at M1 as their local max,
        //   else max over (tied lane contributes m2l, others m1l).
        const int ord1 = f2ord(m1l);
        const int M1o  = warp_max_ord(ord1);
        const bool isM1 = (ord1 == M1o);
        const unsigned bal = __ballot_sync(0xFFFFFFFFu, isM1);
        const int contrib = isM1 ? f2ord(m2l) : ord1;
        int M2o = warp_max_ord(contrib);
        if (__popc(bal) > 1) M2o = M1o;

        const float M1 = ord2f(M1o);
        const float M2 = ord2f(M2o);
        margins[p] = (tv == M1) ? (M1 - M2) : 0.0f;
        if (p < 7) rowmax7o = max(rowmax7o, M1o);
    }

    // softmax over 8 margins with T = 2.0 (computed identically in all lanes)
    float mm = margins[0];
#pragma unroll
    for (int p = 1; p < NPRED; p++) mm = fmaxf(mm, margins[p]);
    float e[NPRED];
    float s = 0.0f;
#pragma unroll
    for (int p = 0; p < NPRED; p++) {
        e[p] = __expf((margins[p] - mm) * 0.5f);
        s += e[p];
    }
    const float inv = 1.0f / s;

    // lanes 0..7 write the 8 softmax outputs (coalesced 32B per row)
    float ov = e[0];
    ov = (lane == 1) ? e[1] : ov;
    ov = (lane == 2) ? e[2] : ov;
    ov = (lane == 3) ? e[3] : ov;
    ov = (lane == 4) ? e[4] : ov;
    ov = (lane == 5) ? e[5] : ov;
    ov = (lane == 6) ? e[6] : ov;
    ov = (lane == 7) ? e[7] : ov;
    if (lane < NPRED) {
        out[1 + row * NPRED + lane] = ov * inv;
    }

    // ---- global max over outputs1..7: block reduce -> 1 atomic/block ----
    __shared__ int sm[WARPS_PER_BLOCK];
    if (lane == 0) sm[warp] = rowmax7o;
    __syncthreads();
    if (threadIdx.x == 0) {
        int bm = sm[0];
#pragma unroll
        for (int i = 1; i < WARPS_PER_BLOCK; i++) bm = max(bm, sm[i]);
        atomicMax(&g_max_bits, bm);
        __threadfence();
        unsigned prev = atomicAdd(&g_blocks_done, 1u);
        if (prev == (unsigned)nblocks - 1u) {
            // last block: publish result and reset scratch for the next replay
            out[0] = ord2f(g_max_bits);
            g_max_bits    = (int)0x80000000;
            g_blocks_done = 0;
        }
    }
}

extern "C" void kernel_launch(void* const* d_in, const int* in_sizes, int n_in,
                              void* d_out, int out_size)
{
    const float* p0  = (const float*)d_in[0];
    const float* p1  = (const float*)d_in[1];
    const float* p2  = (const float*)d_in[2];
    const float* p3  = (const float*)d_in[3];
    const float* p4  = (const float*)d_in[4];
    const float* p5  = (const float*)d_in[5];
    const float* p6  = (const float*)d_in[6];
    const float* mim = (const float*)d_in[7];
    const int*   tg  = (const int*)d_in[8];

    const int N = in_sizes[8];  // targets element count
    float* out = (float*)d_out;

    const int grid = (N + WARPS_PER_BLOCK - 1) / WARPS_PER_BLOCK;
    tw_kernel<<<grid, THREADS>>>(p0, p1, p2, p3, p4, p5, p6, mim, tg, out, grid);
}

// round 4
// speedup vs baseline: 1.0449x; 1.0185x over previous
#include <cuda_runtime.h>
#include <cuda_bf16.h>

#define C               128
#define NPRED           8
#define WARPS_PER_BLOCK 8
#define THREADS         (WARPS_PER_BLOCK * 32)
#define ROWS_PER_BLOCK  (WARPS_PER_BLOCK * 2)   // 2 rows per warp

// Statically-initialized scratch (no allocations allowed). Finalizing block
// resets it -> deterministic across graph replays.
__device__ int      g_max_bits    = (int)0x80000000;
__device__ unsigned g_blocks_done = 0;

__device__ __forceinline__ int f2ord(float x) {
    int i = __float_as_int(x);
    return (i >= 0) ? i : (i ^ 0x7FFFFFFF);
}
__device__ __forceinline__ float ord2f(int i) {
    return __int_as_float((i >= 0) ? i : (i ^ 0x7FFFFFFF));
}

__device__ __forceinline__ float comp(float4 q, int j) {
    return (j == 0) ? q.x : (j == 1) ? q.y : (j == 2) ? q.z : q.w;
}

__global__ __launch_bounds__(THREADS)
void tw_kernel(const float* __restrict__ p0, const float* __restrict__ p1,
               const float* __restrict__ p2, const float* __restrict__ p3,
               const float* __restrict__ p4, const float* __restrict__ p5,
               const float* __restrict__ p6, const float* __restrict__ p7,
               const int*   __restrict__ targets,
               float* __restrict__ out,   // out[0]=max_preds, out+1 = [N,8]
               int nblocks)
{
    const int warp = threadIdx.x >> 5;
    const int lane = threadIdx.x & 31;
    const int grp  = lane >> 4;          // 0/1: which of the warp's 2 rows
    const int lig  = lane & 15;          // lane-in-group, owns 8 columns

    const long long row =
        (long long)blockIdx.x * ROWS_PER_BLOCK + warp * 2 + grp;

    const float* preds[NPRED] = {p0, p1, p2, p3, p4, p5, p6, p7};

    const int t = targets[row];          // group-uniform
    // lane holding column t, within this warp
    const int tsrc = (grp << 4) + ((t & 63) >> 2);
    const int tj   = t & 3;
    const bool thi = (t >= 64);

    // Each lane loads 2 float4 per predictor: columns [lig*4, +4) and [64+lig*4, +4).
    // Per load instr the warp covers 256B of each of its 2 adjacent rows — coalesced.
    // Streaming (read-once).
    const long long base = row * (long long)C + (long long)(lig << 2);
    float4 va[NPRED], vb[NPRED];
#pragma unroll
    for (int p = 0; p < NPRED; p++)
        va[p] = __ldcs(reinterpret_cast<const float4*>(preds[p] + base));
#pragma unroll
    for (int p = 0; p < NPRED; p++)
        vb[p] = __ldcs(reinterpret_cast<const float4*>(preds[p] + base + 64));

    float margins[NPRED];
    float rowmax7 = -3.4e38f;

#pragma unroll
    for (int p = 0; p < NPRED; p++) {
        const float4 qa = va[p];
        const float4 qb = vb[p];

        // local multiset top-2 of this lane's 8 values
        float a1 = fmaxf(qa.x, qa.y), a2 = fminf(qa.x, qa.y);
        float a3 = fmaxf(qa.z, qa.w), a4 = fminf(qa.z, qa.w);
        float m1a = fmaxf(a1, a3);
        float m2a = fmaxf(fminf(a1, a3), fmaxf(a2, a4));

        float b1 = fmaxf(qb.x, qb.y), b2 = fminf(qb.x, qb.y);
        float b3 = fmaxf(qb.z, qb.w), b4 = fminf(qb.z, qb.w);
        float m1b = fmaxf(b1, b3);
        float m2b = fmaxf(fminf(b1, b3), fmaxf(b2, b4));

        float m1 = fmaxf(m1a, m1b);
        float m2 = fmaxf(fminf(m1a, m1b), fmaxf(m2a, m2b));

        // target value: candidate from the owning half, broadcast from owning lane
        float cand = thi ? comp(qb, tj) : comp(qa, tj);
        float tv = __shfl_sync(0xFFFFFFFFu, cand, tsrc);

        // 16-lane multiset top-2 butterfly (stays within the group)
#pragma unroll
        for (int off = 8; off > 0; off >>= 1) {
            float o1 = __shfl_xor_sync(0xFFFFFFFFu, m1, off);
            float o2 = __shfl_xor_sync(0xFFFFFFFFu, m2, off);
            float n1 = fmaxf(m1, o1);
            float n2 = fmaxf(fminf(m1, o1), fmaxf(m2, o2));
            m1 = n1; m2 = n2;
        }

        margins[p] = (tv == m1) ? (m1 - m2) : 0.0f;
        if (p < 7) rowmax7 = fmaxf(rowmax7, m1);
    }

    // softmax over the 8 margins with T = 2.0 (redundant across the 16 group lanes)
    float mm = margins[0];
#pragma unroll
    for (int p = 1; p < NPRED; p++) mm = fmaxf(mm, margins[p]);
    float e[NPRED];
    float s = 0.0f;
#pragma unroll
    for (int p = 0; p < NPRED; p++) {
        e[p] = __expf((margins[p] - mm) * 0.5f);
        s += e[p];
    }
    const float inv = 1.0f / s;

    // group lanes 0..7 write the row's 8 outputs (two adjacent 32B segments/warp)
    float ov = e[0];
    ov = (lig == 1) ? e[1] : ov;
    ov = (lig == 2) ? e[2] : ov;
    ov = (lig == 3) ? e[3] : ov;
    ov = (lig == 4) ? e[4] : ov;
    ov = (lig == 5) ? e[5] : ov;
    ov = (lig == 6) ? e[6] : ov;
    ov = (lig == 7) ? e[7] : ov;
    if (lig < NPRED) {
        out[1 + row * NPRED + lig] = ov * inv;
    }

    // combine the warp's two rows, then block reduce -> 1 atomic/block
    rowmax7 = fmaxf(rowmax7, __shfl_xor_sync(0xFFFFFFFFu, rowmax7, 16));

    __shared__ float sm[WARPS_PER_BLOCK];
    if (lane == 0) sm[warp] = rowmax7;
    __syncthreads();
    if (threadIdx.x == 0) {
        float bm = sm[0];
#pragma unroll
        for (int i = 1; i < WARPS_PER_BLOCK; i++) bm = fmaxf(bm, sm[i]);
        atomicMax(&g_max_bits, f2ord(bm));
        __threadfence();
        unsigned prev = atomicAdd(&g_blocks_done, 1u);
        if (prev == (unsigned)nblocks - 1u) {
            out[0] = ord2f(g_max_bits);
            g_max_bits    = (int)0x80000000;
            g_blocks_done = 0;
        }
    }
}

extern "C" void kernel_launch(void* const* d_in, const int* in_sizes, int n_in,
                              void* d_out, int out_size)
{
    const float* p0  = (const float*)d_in[0];
    const float* p1  = (const float*)d_in[1];
    const float* p2  = (const float*)d_in[2];
    const float* p3  = (const float*)d_in[3];
    const float* p4  = (const float*)d_in[4];
    const float* p5  = (const float*)d_in[5];
    const float* p6  = (const float*)d_in[6];
    const float* mim = (const float*)d_in[7];
    const int*   tg  = (const int*)d_in[8];

    const int N = in_sizes[8];
    float* out = (float*)d_out;

    const int grid = (N + ROWS_PER_BLOCK - 1) / ROWS_PER_BLOCK;
    tw_kernel<<<grid, THREADS>>>(p0, p1, p2, p3, p4, p5, p6, mim, tg, out, grid);
}

// round 5
// speedup vs baseline: 1.0758x; 1.0295x over previous
#include <cuda_runtime.h>
#include <cuda_bf16.h>

#define C               128
#define NPRED           8
#define WARPS_PER_BLOCK 8
#define THREADS         (WARPS_PER_BLOCK * 32)
#define ROWS_PER_BLOCK  (WARPS_PER_BLOCK * 2)   // 2 rows per warp

// Statically-initialized scratch (no allocations allowed). Finalizing block
// resets it -> deterministic across graph replays.
__device__ int      g_max_bits    = (int)0x80000000;
__device__ unsigned g_blocks_done = 0;

__device__ __forceinline__ int f2ord(float x) {
    int i = __float_as_int(x);
    return (i >= 0) ? i : (i ^ 0x7FFFFFFF);
}
__device__ __forceinline__ float ord2f(int i) {
    return __int_as_float((i >= 0) ? i : (i ^ 0x7FFFFFFF));
}

__device__ __forceinline__ float comp(float4 q, int j) {
    return (j == 0) ? q.x : (j == 1) ? q.y : (j == 2) ? q.z : q.w;
}

__global__ __launch_bounds__(THREADS, 4)   // cap regs at 64 -> >=4 blocks/SM
void tw_kernel(const float* __restrict__ p0, const float* __restrict__ p1,
               const float* __restrict__ p2, const float* __restrict__ p3,
               const float* __restrict__ p4, const float* __restrict__ p5,
               const float* __restrict__ p6, const float* __restrict__ p7,
               const int*   __restrict__ targets,
               float* __restrict__ out,   // out[0]=max_preds, out+1 = [N,8]
               int nblocks)
{
    const int warp = threadIdx.x >> 5;
    const int lane = threadIdx.x & 31;
    const int grp  = lane >> 4;          // 0/1: which of the warp's 2 rows
    const int lig  = lane & 15;          // lane-in-group, owns 8 columns

    const long long row =
        (long long)blockIdx.x * ROWS_PER_BLOCK + warp * 2 + grp;

    const float* preds[NPRED] = {p0, p1, p2, p3, p4, p5, p6, p7};

    const int t = targets[row];          // group-uniform
    const int tsrc = (grp << 4) + ((t & 63) >> 2);  // warp lane holding column t
    const int tj   = t & 3;
    const bool thi = (t >= 64);

    const long long base = row * (long long)C + (long long)(lig << 2);

    float margins[NPRED];
    float rowmax7 = -3.4e38f;

    // Two batches of 4 predictors: only 8 float4 (32 regs) live at once,
    // so occupancy stays high; the inter-batch memory bubble is covered by
    // the extra concurrent warps.
#pragma unroll
    for (int b = 0; b < 2; b++) {
        float4 va[4], vb[4];
#pragma unroll
        for (int i = 0; i < 4; i++)
            va[i] = __ldcs(reinterpret_cast<const float4*>(preds[b * 4 + i] + base));
#pragma unroll
        for (int i = 0; i < 4; i++)
            vb[i] = __ldcs(reinterpret_cast<const float4*>(preds[b * 4 + i] + base + 64));

#pragma unroll
        for (int i = 0; i < 4; i++) {
            const int p = b * 4 + i;
            const float4 qa = va[i];
            const float4 qb = vb[i];

            // local multiset top-2 of this lane's 8 values
            float a1 = fmaxf(qa.x, qa.y), a2 = fminf(qa.x, qa.y);
            float a3 = fmaxf(qa.z, qa.w), a4 = fminf(qa.z, qa.w);
            float m1a = fmaxf(a1, a3);
            float m2a = fmaxf(fminf(a1, a3), fmaxf(a2, a4));

            float b1 = fmaxf(qb.x, qb.y), b2 = fminf(qb.x, qb.y);
            float b3 = fmaxf(qb.z, qb.w), b4 = fminf(qb.z, qb.w);
            float m1b = fmaxf(b1, b3);
            float m2b = fmaxf(fminf(b1, b3), fmaxf(b2, b4));

            float m1 = fmaxf(m1a, m1b);
            float m2 = fmaxf(fminf(m1a, m1b), fmaxf(m2a, m2b));

            // target value: candidate from owning half, broadcast from owning lane
            float cand = thi ? comp(qb, tj) : comp(qa, tj);
            float tv = __shfl_sync(0xFFFFFFFFu, cand, tsrc);

            // 16-lane multiset top-2 butterfly (stays within the group)
#pragma unroll
            for (int off = 8; off > 0; off >>= 1) {
                float o1 = __shfl_xor_sync(0xFFFFFFFFu, m1, off);
                float o2 = __shfl_xor_sync(0xFFFFFFFFu, m2, off);
                float n1 = fmaxf(m1, o1);
                float n2 = fmaxf(fminf(m1, o1), fmaxf(m2, o2));
                m1 = n1; m2 = n2;
            }

            margins[p] = (tv == m1) ? (m1 - m2) : 0.0f;
            if (p < 7) rowmax7 = fmaxf(rowmax7, m1);
        }
        // stop ptxas from hoisting batch-1 loads into batch 0 (reg blow-up)
        asm volatile("" ::: "memory");
    }

    // softmax over the 8 margins with T = 2.0 (redundant across group lanes)
    float mm = margins[0];
#pragma unroll
    for (int p = 1; p < NPRED; p++) mm = fmaxf(mm, margins[p]);
    float e[NPRED];
    float s = 0.0f;
#pragma unroll
    for (int p = 0; p < NPRED; p++) {
        e[p] = __expf((margins[p] - mm) * 0.5f);
        s += e[p];
    }
    const float inv = 1.0f / s;

    // group lanes 0..7 write the row's 8 outputs
    float ov = e[0];
    ov = (lig == 1) ? e[1] : ov;
    ov = (lig == 2) ? e[2] : ov;
    ov = (lig == 3) ? e[3] : ov;
    ov = (lig == 4) ? e[4] : ov;
    ov = (lig == 5) ? e[5] : ov;
    ov = (lig == 6) ? e[6] : ov;
    ov = (lig == 7) ? e[7] : ov;
    if (lig < NPRED) {
        out[1 + row * NPRED + lig] = ov * inv;
    }

    // combine the warp's two rows, then block reduce -> 1 atomic/block
    rowmax7 = fmaxf(rowmax7, __shfl_xor_sync(0xFFFFFFFFu, rowmax7, 16));

    __shared__ float sm[WARPS_PER_BLOCK];
    if (lane == 0) sm[warp] = rowmax7;
    __syncthreads();
    if (threadIdx.x == 0) {
        float bm = sm[0];
#pragma unroll
        for (int i = 1; i < WARPS_PER_BLOCK; i++) bm = fmaxf(bm, sm[i]);
        atomicMax(&g_max_bits, f2ord(bm));
        __threadfence();
        unsigned prev = atomicAdd(&g_blocks_done, 1u);
        if (prev == (unsigned)nblocks - 1u) {
            out[0] = ord2f(g_max_bits);
            g_max_bits    = (int)0x80000000;
            g_blocks_done = 0;
        }
    }
}

extern "C" void kernel_launch(void* const* d_in, const int* in_sizes, int n_in,
                              void* d_out, int out_size)
{
    const float* p0  = (const float*)d_in[0];
    const float* p1  = (const float*)d_in[1];
    const float* p2  = (const float*)d_in[2];
    const float* p3  = (const float*)d_in[3];
    const float* p4  = (const float*)d_in[4];
    const float* p5  = (const float*)d_in[5];
    const float* p6  = (const float*)d_in[6];
    const float* mim = (const float*)d_in[7];
    const int*   tg  = (const int*)d_in[8];

    const int N = in_sizes[8];
    float* out = (float*)d_out;

    const int grid = (N + ROWS_PER_BLOCK - 1) / ROWS_PER_BLOCK;
    tw_kernel<<<grid, THREADS>>>(p0, p1, p2, p3, p4, p5, p6, mim, tg, out, grid);
}